// round 13
// baseline (speedup 1.0000x reference)
#include <cuda_runtime.h>

#define NPTS 4096
#define NB   8
#define KNN  20
#define CO   64
#define CTA  256
#define Q2   2
#define ITER 16             // point-iterations per thread
#define PREI 2              // calibration iterations (512 points)
#define CAP  1024           // candidates per query
#define TCAP 64

__device__ float4 g_xp[NB * NPTS];   // {x, y, z, -0.5*|p|^2}
__device__ float4 g_wf[CO * 2];      // per o: {w0,w1,w2,w3}, {w4,w5,inv,shift}

__global__ void prep_kernel(const float* __restrict__ x,
                            const float* __restrict__ W,
                            const float* __restrict__ gamma_,
                            const float* __restrict__ beta_,
                            const float* __restrict__ mean_,
                            const float* __restrict__ var_)
{
    int idx = blockIdx.x * blockDim.x + threadIdx.x;
    if (idx < NB * NPTS) {
        int b = idx >> 12, p = idx & (NPTS - 1);
        const float* xb = x + (size_t)b * 3 * NPTS;
        float px = xb[p], py = xb[NPTS + p], pz = xb[2 * NPTS + p];
        g_xp[idx] = make_float4(px, py, pz, -0.5f * (px*px + py*py + pz*pz));
    }
    if (blockIdx.x == 0 && threadIdx.x < CO) {
        int o = threadIdx.x;
        float inv   = gamma_[o] * rsqrtf(var_[o] + 1e-5f);
        float shift = beta_[o] - mean_[o] * inv;
        g_wf[2*o]   = make_float4(W[6*o+0], W[6*o+1], W[6*o+2], W[6*o+3]);
        g_wf[2*o+1] = make_float4(W[6*o+4], W[6*o+5], inv, shift);
    }
}

// key: monotone-uint of pd/2. Bit-exact on recompute (same fmaf chain).
__device__ __forceinline__ unsigned keyof(const float4& q, const float4& v)
{
    float s = q.w + v.w;
    s = fmaf(q.x, v.x, fmaf(q.y, v.y, fmaf(q.z, v.z, s)));
    unsigned bb = __float_as_uint(s);
    return bb ^ (unsigned)(((int)bb >> 31) | 0x80000000);
}

// Warp-level descending suffix scan over 256 bins; exactly one lane gets sel>=0.
__device__ __forceinline__ void warp_scan_select(const int* h, int needv,
                                                 int& selBin, int& selBefore, int& selCnt)
{
    int lane = threadIdx.x & 31;
    int base = 255 - (lane << 3);
    int c[8]; int tsum = 0;
    #pragma unroll
    for (int j = 0; j < 8; j++) { c[j] = h[base - j]; tsum += c[j]; }
    int cum = tsum;
    #pragma unroll
    for (int off = 1; off < 32; off <<= 1) {
        int t = __shfl_up_sync(0xffffffffu, cum, off);
        if (lane >= off) cum += t;
    }
    int cumBefore = cum - tsum;
    selBin = -1;
    if (cumBefore < needv && needv <= cum) {
        int acc = cumBefore;
        #pragma unroll
        for (int j = 0; j < 8; j++) {
            if (acc + c[j] >= needv) { selBin = base - j; selBefore = acc; selCnt = c[j]; break; }
            acc += c[j];
        }
    }
}

__global__ __launch_bounds__(CTA)
void edgeconv_kernel(float* __restrict__ out)
{
    __shared__ int                hist[Q2][256];       // 2 KB
    __shared__ unsigned long long cand[Q2][CAP];       // 16 KB
    __shared__ unsigned long long tieb[Q2][TCAP];      // 1 KB
    __shared__ int                knn_s[Q2][KNN];
    __shared__ float4             nbr[Q2][KNN];
    __shared__ int pb_s[Q2], need_s[Q2], cnt_s[Q2], sh_s[Q2];
    __shared__ unsigned pf_s[Q2];
    __shared__ int cntC[Q2], cntW[Q2], cntT[Q2];

    const int b    = blockIdx.y;
    const int n0   = blockIdx.x * Q2;
    const int tid  = threadIdx.x;
    const int lane = tid & 31;
    const int wid  = tid >> 5;
    unsigned lt_mask; asm("mov.u32 %0, %%lanemask_lt;" : "=r"(lt_mask));

    const float4* __restrict__ xp = g_xp + (size_t)b * NPTS;
    const float4 q0 = xp[n0];
    const float4 q1 = xp[n0 + 1];

    #pragma unroll
    for (int i = 0; i < (Q2 * 256) / CTA; i++) ((int*)hist)[i * CTA + tid] = 0;
    if (tid < Q2) { cntC[tid] = 0; cntW[tid] = 0; cntT[tid] = 0; sh_s[tid] = 24; need_s[tid] = KNN; }
    __syncthreads();

    // ---- phase A: calibration (512 points) — full match-aggregated hist
    #pragma unroll
    for (int i = 0; i < PREI; i++) {
        float4 v = xp[i * CTA + tid];
        #pragma unroll
        for (int j = 0; j < Q2; j++) {
            unsigned u = keyof(j ? q1 : q0, v);
            int bin = (int)(u >> 24);
            unsigned mk = __match_any_sync(0xffffffffu, bin);
            if (!(mk & lt_mask)) atomicAdd(&hist[j][bin], __popc(mk));
        }
    }
    __syncthreads();

    // ---- provisional thresholds pb[j] (warps 0 and 1)
    if (wid < Q2) {
        int sb, sbefore, scnt;
        warp_scan_select(hist[wid], KNN, sb, sbefore, scnt);
        if (sb >= 0) pb_s[wid] = sb;
    }
    __syncthreads();

    const int pb0 = pb_s[0], pb1 = pb_s[1];

    // ---- re-zero hist (rebuilt from candidates later)
    #pragma unroll
    for (int i = 0; i < (Q2 * 256) / CTA; i++) ((int*)hist)[i * CTA + tid] = 0;

    // ---- phase B: full sweep, ballot-aggregated candidate appends, no hist
    #pragma unroll 4
    for (int i = 0; i < ITER; i++) {
        int p = i * CTA + tid;
        float4 v = xp[p];
        #pragma unroll
        for (int j = 0; j < Q2; j++) {
            unsigned u = keyof(j ? q1 : q0, v);
            bool pass = (int)(u >> 24) >= (j ? pb1 : pb0);
            unsigned bal = __ballot_sync(0xffffffffu, pass);
            if (bal) {
                int leader = __ffs(bal) - 1;
                int base = 0;
                if (lane == leader) base = atomicAdd(&cntC[j], __popc(bal));
                base = __shfl_sync(0xffffffffu, base, leader);
                if (pass) {
                    int pos = base + __popc(bal & lt_mask);
                    if (pos < CAP)
                        cand[j][pos] = ((unsigned long long)u << 16)
                                     | (unsigned long long)(0xFFFFu - (unsigned)p);
                }
            }
        }
    }
    __syncthreads();

    const bool ovf0 = cntC[0] > CAP, ovf1 = cntC[1] > CAP;

    // ---- histogram from candidates (exact for bins >= pb); rescan if overflowed
    #pragma unroll
    for (int j = 0; j < Q2; j++) {
        bool ovf = j ? ovf1 : ovf0;
        if (!ovf) {
            int cc = cntC[j];
            int rounds = (cc + CTA - 1) / CTA;
            for (int r = 0; r < rounds; r++) {
                int e = r * CTA + tid;
                bool act = e < cc;
                int bin = act ? (int)(cand[j][e] >> 40) : -1;
                unsigned mk = __match_any_sync(0xffffffffu, bin);
                if (act && !(mk & lt_mask)) atomicAdd(&hist[j][bin], __popc(mk));
            }
        } else {
            int pbj = j ? pb1 : pb0;
            #pragma unroll
            for (int i = 0; i < ITER; i++) {
                unsigned u = keyof(j ? q1 : q0, xp[i * CTA + tid]);
                int bin = (int)(u >> 24);
                if (bin >= pbj) atomicAdd(&hist[j][bin], 1);
            }
        }
    }
    __syncthreads();

    // ---- final thresholds (warps 0 and 1)
    if (wid < Q2) {
        int sb, sbefore, scnt;
        warp_scan_select(hist[wid], KNN, sb, sbefore, scnt);
        if (sb >= 0) {
            pf_s[wid]   = (unsigned)sb;
            need_s[wid] = KNN - sbefore;
            cnt_s[wid]  = scnt;
        }
    }
    __syncthreads();

    // ---- refine (rare), per query, snapshot-disciplined
    #pragma unroll
    for (int j = 0; j < Q2; j++) {
        bool ovf = j ? ovf1 : ovf0;
        while (cnt_s[j] > TCAP && sh_s[j] > 0) {
            const unsigned pf    = pf_s[j];
            const int      sh    = sh_s[j];
            const int      nsh   = sh - 8;
            const int      needv = need_s[j];
            __syncthreads();
            hist[j][tid & 255] = 0;           // 256 threads cover all bins
            __syncthreads();
            if (!ovf) {
                int cc = cntC[j];
                for (int e = tid; e < cc; e += CTA) {
                    unsigned u = (unsigned)(cand[j][e] >> 16);
                    if ((u >> sh) == pf) atomicAdd(&hist[j][(u >> nsh) & 255u], 1);
                }
            } else {
                #pragma unroll
                for (int i = 0; i < ITER; i++) {
                    unsigned u = keyof(j ? q1 : q0, xp[i * CTA + tid]);
                    if ((u >> sh) == pf) atomicAdd(&hist[j][(u >> nsh) & 255u], 1);
                }
            }
            __syncthreads();
            if (wid == 0) {
                int sb, sbefore, scnt;
                warp_scan_select(hist[j], needv, sb, sbefore, scnt);
                if (sb >= 0) {
                    pf_s[j]   = (pf << 8) | (unsigned)sb;
                    sh_s[j]   = nsh;
                    need_s[j] = needv - sbefore;
                    cnt_s[j]  = scnt;
                }
            }
            __syncthreads();
        }
    }

    // ---- collect winners + boundary ties
    #pragma unroll
    for (int j = 0; j < Q2; j++) {
        bool ovf = j ? ovf1 : ovf0;
        const unsigned pf = pf_s[j];
        const int      sh = sh_s[j];
        if (!ovf) {
            int cc = cntC[j];
            for (int e = tid; e < cc; e += CTA) {
                unsigned long long pk = cand[j][e];
                unsigned u  = (unsigned)(pk >> 16);
                unsigned hi = u >> sh;
                if (hi >= pf) {
                    if (hi > pf) {
                        knn_s[j][atomicAdd(&cntW[j], 1)] = 0xFFFF - (int)(pk & 0xFFFFu);
                    } else {
                        int pos = atomicAdd(&cntT[j], 1);
                        if (pos < TCAP) tieb[j][pos] = pk;
                    }
                }
            }
        } else {
            #pragma unroll
            for (int i = 0; i < ITER; i++) {
                int p = i * CTA + tid;
                unsigned u  = keyof(j ? q1 : q0, xp[p]);
                unsigned hi = u >> sh;
                if (hi >= pf) {
                    if (hi > pf) {
                        knn_s[j][atomicAdd(&cntW[j], 1)] = p;
                    } else {
                        int pos = atomicAdd(&cntT[j], 1);
                        if (pos < TCAP)
                            tieb[j][pos] = ((unsigned long long)u << 16)
                                         | (unsigned long long)(0xFFFFu - (unsigned)p);
                    }
                }
            }
        }
    }
    __syncthreads();

    // ---- tie rank (warp j handles query j): packed u64 encodes (key desc, idx asc)
    if (wid < Q2) {
        int j = wid;
        int cnt   = cntT[j] < TCAP ? cntT[j] : TCAP;
        int needv = need_s[j];
        int baseW = cntW[j];
        for (int e = lane; e < cnt; e += 32) {
            unsigned long long mine = tieb[j][e];
            int rank = 0;
            for (int t2 = 0; t2 < cnt; t2++) rank += (tieb[j][t2] > mine);
            if (rank < needv) knn_s[j][baseW + rank] = 0xFFFF - (int)(mine & 0xFFFFu);
        }
    }
    __syncthreads();

    // ---- gather neighbor coords
    if (tid < Q2 * KNN) {
        int j = tid / KNN, k = tid % KNN;
        nbr[j][k] = xp[knn_s[j][k]];
    }
    __syncthreads();

    // ---- edge MLP: 128 outputs, 2 threads each (10 k's), shfl-combine
    {
        const int j = tid >> 7;            // warp-uniform
        const int o = (tid >> 1) & 63;
        const int c = tid & 1;
        const float4 qv = j ? q1 : q0;
        const float4 wa = g_wf[2*o];
        const float4 wb = g_wf[2*o + 1];
        const float cpart = fmaf(qv.x, wa.w, fmaf(qv.y, wb.x, qv.z * wb.y));

        float m = -3.4028235e38f;
        #pragma unroll
        for (int k = 0; k < KNN / 2; k++) {
            float4 p = nbr[j][k * 2 + c];
            float y = fmaf(p.x - qv.x, wa.x,
                      fmaf(p.y - qv.y, wa.y,
                      fmaf(p.z - qv.z, wa.z, cpart)));
            y = fmaf(y, wb.z, wb.w);
            y = (y >= 0.0f) ? y : 0.2f * y;
            m = fmaxf(m, y);
        }
        m = fmaxf(m, __shfl_xor_sync(0xffffffffu, m, 1));
        if (c == 0)
            out[(size_t)b * CO * NPTS + (size_t)o * NPTS + n0 + j] = m;
    }
}

extern "C" void kernel_launch(void* const* d_in, const int* in_sizes, int n_in,
                              void* d_out, int out_size)
{
    const float* x      = (const float*)d_in[0];
    const float* W      = (const float*)d_in[1];
    const float* gamma_ = (const float*)d_in[2];
    const float* beta_  = (const float*)d_in[3];
    const float* mean_  = (const float*)d_in[4];
    const float* var_   = (const float*)d_in[5];
    float* out = (float*)d_out;

    prep_kernel<<<(NB * NPTS + 255) / 256, 256>>>(x, W, gamma_, beta_, mean_, var_);
    dim3 grid(NPTS / Q2, NB);
    edgeconv_kernel<<<grid, CTA>>>(out);
}

// round 14
// speedup vs baseline: 1.2915x; 1.2915x over previous
#include <cuda_runtime.h>

#define NPTS 4096
#define NB   8
#define KNN  20
#define CO   64
#define CTA  256
#define SLOTS 16            // keys per thread (in smem)
#define PREI  2             // calibration iterations (512 points)
#define TIE_CAP 128

__device__ float4 g_xp[NB * NPTS];   // {x, y, z, -0.5*|p|^2}
__device__ float4 g_wf[CO * 2];      // per o: {w0,w1,w2,w3}, {w4,w5,inv,shift}

__global__ void prep_kernel(const float* __restrict__ x,
                            const float* __restrict__ W,
                            const float* __restrict__ gamma_,
                            const float* __restrict__ beta_,
                            const float* __restrict__ mean_,
                            const float* __restrict__ var_)
{
    int idx = blockIdx.x * blockDim.x + threadIdx.x;
    if (idx < NB * NPTS) {
        int b = idx >> 12, p = idx & (NPTS - 1);
        const float* xb = x + (size_t)b * 3 * NPTS;
        float px = xb[p], py = xb[NPTS + p], pz = xb[2 * NPTS + p];
        g_xp[idx] = make_float4(px, py, pz, -0.5f * (px*px + py*py + pz*pz));
    }
    if (blockIdx.x == 0 && threadIdx.x < CO) {
        int o = threadIdx.x;
        float inv   = gamma_[o] * rsqrtf(var_[o] + 1e-5f);
        float shift = beta_[o] - mean_[o] * inv;
        g_wf[2*o]   = make_float4(W[6*o+0], W[6*o+1], W[6*o+2], W[6*o+3]);
        g_wf[2*o+1] = make_float4(W[6*o+4], W[6*o+5], inv, shift);
    }
}

__global__ __launch_bounds__(CTA, 8)      // force 32-reg budget -> 8 CTAs/SM
void edgeconv_kernel(float* __restrict__ out)
{
    __shared__ unsigned keysu[NPTS];       // 16 KB
    __shared__ int      hist[256];
    __shared__ int      warpTot[8], warpOff[8];
    __shared__ int      knn_s[KNN];
    __shared__ float4   nbr[KNN];
    __shared__ int      tie_idx[TIE_CAP];
    __shared__ unsigned tie_key[TIE_CAP];
    __shared__ int      s_cntW, s_cntT, s_need, s_cnt, s_shift, s_pb;
    __shared__ unsigned s_prefix;

    const int b    = blockIdx.y;
    const int n    = blockIdx.x;
    const int tid  = threadIdx.x;
    const int lane = tid & 31;
    const int wid  = tid >> 5;
    unsigned lt_mask; asm("mov.u32 %0, %%lanemask_lt;" : "=r"(lt_mask));

    const float4* __restrict__ xp = g_xp + (size_t)b * NPTS;
    const float4 q = xp[n];

    hist[tid] = 0;
    if (tid == 0) { s_cntW = 0; s_cntT = 0; s_need = KNN; s_cnt = 0; s_shift = 24; }
    __syncthreads();

    // ---- phase 1a: first 512 keys -> smem + full match-aggregated hist insert
    #pragma unroll
    for (int i = 0; i < PREI; i++) {
        int p = i * CTA + tid;
        float4 v = xp[p];
        float s = q.w + v.w;
        s = fmaf(q.x, v.x, fmaf(q.y, v.y, fmaf(q.z, v.z, s)));
        unsigned bb = __float_as_uint(s);
        unsigned u  = bb ^ (unsigned)(((int)bb >> 31) | 0x80000000);
        keysu[p] = u;
        int bin = (int)(u >> 24);
        unsigned mk = __match_any_sync(0xffffffffu, bin);
        if (!(mk & lt_mask)) atomicAdd(&hist[bin], __popc(mk));
    }
    __syncthreads();

    // ---- provisional threshold pb (exact lower bound on final threshold bin)
    {
        int binv = hist[255 - tid];
        int cum = binv;
        #pragma unroll
        for (int off = 1; off < 32; off <<= 1) {
            int t = __shfl_up_sync(0xffffffffu, cum, off);
            if (lane >= off) cum += t;
        }
        if (lane == 31) warpTot[wid] = cum;
        __syncthreads();
        if (wid == 0) {
            int v = (lane < 8) ? warpTot[lane] : 0;
            int cc = v;
            #pragma unroll
            for (int off = 1; off < 8; off <<= 1) {
                int t = __shfl_up_sync(0xffffffffu, cc, off);
                if (lane >= off) cc += t;
            }
            if (lane < 8) warpOff[lane] = cc - v;
        }
        __syncthreads();
        int cumAll    = cum + warpOff[wid];
        int cumBefore = cumAll - binv;
        if (cumBefore < KNN && KNN <= cumAll) s_pb = 255 - tid;
        __syncthreads();
    }
    const int pb = s_pb;

    // ---- phase 1b: remaining keys -> smem; hist insert ONLY for bins >= pb
    #pragma unroll 4
    for (int i = PREI; i < SLOTS; i++) {
        int p = i * CTA + tid;
        float4 v = xp[p];
        float s = q.w + v.w;
        s = fmaf(q.x, v.x, fmaf(q.y, v.y, fmaf(q.z, v.z, s)));
        unsigned bb = __float_as_uint(s);
        unsigned u  = bb ^ (unsigned)(((int)bb >> 31) | 0x80000000);
        keysu[p] = u;
        int bin = (int)(u >> 24);
        if (bin >= pb) atomicAdd(&hist[bin], 1);
    }
    __syncthreads();

    // ---- block-wide descending suffix scan (bins >= pb exact; threshold >= pb)
    {
        int binv = hist[255 - tid];
        int cum = binv;
        #pragma unroll
        for (int off = 1; off < 32; off <<= 1) {
            int t = __shfl_up_sync(0xffffffffu, cum, off);
            if (lane >= off) cum += t;
        }
        if (lane == 31) warpTot[wid] = cum;
        __syncthreads();
        if (wid == 0) {
            int v = (lane < 8) ? warpTot[lane] : 0;
            int cc = v;
            #pragma unroll
            for (int off = 1; off < 8; off <<= 1) {
                int t = __shfl_up_sync(0xffffffffu, cc, off);
                if (lane >= off) cc += t;
            }
            if (lane < 8) warpOff[lane] = cc - v;
        }
        __syncthreads();
        int cumAll    = cum + warpOff[wid];
        int cumBefore = cumAll - binv;
        if (cumBefore < KNN && KNN <= cumAll) {
            s_prefix = (unsigned)(255 - tid);
            s_need   = KNN - cumBefore;
            s_cnt    = binv;
        }
    }
    __syncthreads();

    // ---- fallback: refine threshold bin by 8 bits at a time (snapshot-disciplined)
    while (s_cnt > TIE_CAP && s_shift > 0) {
        const unsigned pf    = s_prefix;
        const int      sh    = s_shift;
        const int      nsh   = sh - 8;
        const int      needv = s_need;
        __syncthreads();
        hist[tid] = 0;
        __syncthreads();
        #pragma unroll 4
        for (int i = 0; i < SLOTS; i++) {
            unsigned u = keysu[i * CTA + tid];
            bool valid = (u >> sh) == pf;
            int bin = valid ? (int)((u >> nsh) & 255u) : -1;
            unsigned mk = __match_any_sync(0xffffffffu, bin);
            if (valid && !(mk & lt_mask)) atomicAdd(&hist[bin], __popc(mk));
        }
        __syncthreads();
        {
            int binv = hist[255 - tid];
            int cum = binv;
            #pragma unroll
            for (int off = 1; off < 32; off <<= 1) {
                int t = __shfl_up_sync(0xffffffffu, cum, off);
                if (lane >= off) cum += t;
            }
            if (lane == 31) warpTot[wid] = cum;
            __syncthreads();
            if (wid == 0) {
                int v = (lane < 8) ? warpTot[lane] : 0;
                int cc = v;
                #pragma unroll
                for (int off = 1; off < 8; off <<= 1) {
                    int t = __shfl_up_sync(0xffffffffu, cc, off);
                    if (lane >= off) cc += t;
                }
                if (lane < 8) warpOff[lane] = cc - v;
            }
            __syncthreads();
            int cumAll    = cum + warpOff[wid];
            int cumBefore = cumAll - binv;
            if (cumBefore < needv && needv <= cumAll) {
                s_prefix = (pf << 8) | (unsigned)(255 - tid);
                s_need   = needv - cumBefore;
                s_cnt    = binv;
                s_shift  = nsh;
            }
        }
        __syncthreads();
    }

    // ---- collect winners (unordered set) + boundary-bin tie candidates
    {
        const int      sh = s_shift;
        const unsigned pf = s_prefix;
        #pragma unroll 4
        for (int i = 0; i < SLOTS; i++) {
            int p = i * CTA + tid;
            unsigned u  = keysu[p];
            unsigned hi = u >> sh;
            if (hi >= pf) {
                if (hi > pf) {
                    knn_s[atomicAdd(&s_cntW, 1)] = p;
                } else {
                    int pos = atomicAdd(&s_cntT, 1);
                    if (pos < TIE_CAP) { tie_idx[pos] = p; tie_key[pos] = u; }
                }
            }
        }
    }
    __syncthreads();

    // ---- parallel exact tie resolve: rank by (value desc, index asc)
    {
        int cnt   = s_cntT < TIE_CAP ? s_cntT : TIE_CAP;
        int needf = s_need;
        int baseW = s_cntW;
        if (tid < cnt) {
            unsigned mk = tie_key[tid]; int mi = tie_idx[tid];
            int rank = 0;
            for (int j = 0; j < cnt; j++) {
                unsigned kj = tie_key[j]; int ij = tie_idx[j];
                rank += (kj > mk) || (kj == mk && ij < mi);
            }
            if (rank < needf) knn_s[baseW + rank] = mi;
        }
    }
    __syncthreads();

    // ---- gather neighbor coords
    if (tid < KNN) nbr[tid] = xp[knn_s[tid]];
    __syncthreads();

    // ---- edge MLP: 4 threads per output channel, 5 k's each, shfl-combine
    {
        const int o = tid >> 2;
        const int c = tid & 3;
        const float4 wa = g_wf[2*o];      // w0 w1 w2 w3
        const float4 wb = g_wf[2*o + 1];  // w4 w5 inv shift
        const float cpart = fmaf(q.x, wa.w, fmaf(q.y, wb.x, q.z * wb.y));

        float m = -3.4028235e38f;
        #pragma unroll
        for (int k = 0; k < 5; k++) {
            float4 p = nbr[c * 5 + k];
            float y = fmaf(p.x - q.x, wa.x,
                      fmaf(p.y - q.y, wa.y,
                      fmaf(p.z - q.z, wa.z, cpart)));
            y = fmaf(y, wb.z, wb.w);
            y = (y >= 0.0f) ? y : 0.2f * y;
            m = fmaxf(m, y);
        }
        m = fmaxf(m, __shfl_xor_sync(0xffffffffu, m, 1));
        m = fmaxf(m, __shfl_xor_sync(0xffffffffu, m, 2));
        if (c == 0)
            out[(size_t)b * CO * NPTS + (size_t)o * NPTS + n] = m;
    }
}

extern "C" void kernel_launch(void* const* d_in, const int* in_sizes, int n_in,
                              void* d_out, int out_size)
{
    const float* x      = (const float*)d_in[0];
    const float* W      = (const float*)d_in[1];
    const float* gamma_ = (const float*)d_in[2];
    const float* beta_  = (const float*)d_in[3];
    const float* mean_  = (const float*)d_in[4];
    const float* var_   = (const float*)d_in[5];
    float* out = (float*)d_out;

    prep_kernel<<<(NB * NPTS + 255) / 256, 256>>>(x, W, gamma_, beta_, mean_, var_);
    dim3 grid(NPTS, NB);
    edgeconv_kernel<<<grid, CTA>>>(out);
}